// round 2
// baseline (speedup 1.0000x reference)
#include <cuda_runtime.h>
#include <math.h>

#define Bq   8
#define Hq   8
#define Lq   2048
#define Dq   64
#define Uq   40
#define BH   64
#define CTXN (BH*Uq*Dq)
#define NCH  8

// scratch (no allocations allowed)
__device__ float g_M[BH*Lq];
__device__ int   g_top[BH*Uq];
__device__ float g_part[NCH*CTXN];

// ---------------------------------------------------------------------------
// Kernel 1: M[bh,l] = max_s(q·k[idx]) - sum_s(q·k[idx]) / L
// Warp per (bh,l); LANE-PER-SAMPLE: lane s computes the full dot for sample s
// via 16 independent LDG.128 (MLP=16). One max+sum shfl reduction per l.
// ---------------------------------------------------------------------------
__global__ __launch_bounds__(256) void k_M(const float* __restrict__ q,
                                           const float* __restrict__ kk,
                                           const int* __restrict__ idx) {
    int gw   = (blockIdx.x * blockDim.x + threadIdx.x) >> 5;   // bh*Lq + l
    int lane = threadIdx.x & 31;
    int bh = gw >> 11;
    int l  = gw & (Lq - 1);

    const float* kbase = kk + (size_t)bh*Lq*Dq;
    const float4* qrow = (const float4*)(q + ((size_t)bh*Lq + l)*Dq);

    // sample indices: lane handles s=lane, and (lane<8) also s=32+lane
    int jA = __ldg(idx + l*Uq + lane);
    const float4* kA = (const float4*)(kbase + (size_t)jA*Dq);

    float pA = 0.f;
    #pragma unroll
    for (int c = 0; c < 16; ++c) {
        float4 qv = __ldg(qrow + c);          // broadcast, L1-hit
        float4 a  = __ldg(kA + c);            // 16 independent gathers/lane
        pA = fmaf(qv.x, a.x, fmaf(qv.y, a.y, fmaf(qv.z, a.z, fmaf(qv.w, a.w, pA))));
    }

    float pB = 0.f;
    bool hasB = (lane < (Uq - 32));
    if (hasB) {
        int jB = __ldg(idx + l*Uq + 32 + lane);
        const float4* kB = (const float4*)(kbase + (size_t)jB*Dq);
        #pragma unroll
        for (int c = 0; c < 16; ++c) {
            float4 qv = __ldg(qrow + c);
            float4 b  = __ldg(kB + c);
            pB = fmaf(qv.x, b.x, fmaf(qv.y, b.y, fmaf(qv.z, b.z, fmaf(qv.w, b.w, pB))));
        }
    }

    float s = pA + pB;                              // pB==0 when !hasB
    float m = hasB ? fmaxf(pA, pB) : pA;
    #pragma unroll
    for (int o = 16; o > 0; o >>= 1) {
        s += __shfl_xor_sync(0xffffffffu, s, o);
        m  = fmaxf(m, __shfl_xor_sync(0xffffffffu, m, o));
    }
    if (lane == 0) g_M[gw] = m - s * (1.0f / (float)Lq);
}

// ---------------------------------------------------------------------------
// Kernel 2: top-40 of M per (bh), descending, ties -> lower index (jax order)
// ---------------------------------------------------------------------------
__global__ void k_topk() {
    __shared__ float sv[Lq];
    __shared__ float rv[256];
    __shared__ int   ri[256];
    int bh = blockIdx.x, t = threadIdx.x;

    for (int i = t; i < Lq; i += 256) sv[i] = g_M[bh*Lq + i];
    __syncthreads();

    for (int r = 0; r < Uq; ++r) {
        float bv = -INFINITY; int bi = Lq;
        for (int i = t; i < Lq; i += 256) {
            float x = sv[i];
            if (x > bv || (x == bv && i < bi)) { bv = x; bi = i; }
        }
        rv[t] = bv; ri[t] = bi;
        __syncthreads();
        for (int o = 128; o > 0; o >>= 1) {
            if (t < o) {
                float x = rv[t+o]; int j = ri[t+o];
                if (x > rv[t] || (x == rv[t] && j < ri[t])) { rv[t] = x; ri[t] = j; }
            }
            __syncthreads();
        }
        if (t == 0) { g_top[bh*Uq + r] = ri[0]; sv[ri[0]] = -INFINITY; }
        __syncthreads();
    }
}

// ---------------------------------------------------------------------------
// Kernel 3: raw scaled scores -> attn buffer.  Block = (bh, 128-key tile).
// ---------------------------------------------------------------------------
__global__ void k_scores(const float* __restrict__ q, const float* __restrict__ kk,
                         float* __restrict__ attn) {
    __shared__ float4 qs[Uq][16];    // 40 x 64 f32
    __shared__ float4 ks[128][17];   // 128 x 64 f32, padded
    int bh = blockIdx.y, tile = blockIdx.x, t = threadIdx.x;

    const float* qb = q  + (size_t)bh*Lq*Dq;
    const float* kb = kk + ((size_t)bh*Lq + tile*128)*Dq;

    for (int i = t; i < Uq*Dq; i += 256) {
        int r = i >> 6, d = i & 63;
        ((float*)&qs[r][0])[d] = qb[(size_t)g_top[bh*Uq + r]*Dq + d];
    }
    for (int i = t; i < 128*16; i += 256)
        ks[i >> 4][i & 15] = ((const float4*)kb)[i];
    __syncthreads();

    for (int p = t; p < Uq*128; p += 256) {
        int i = p >> 7, l = p & 127;
        float acc = 0.f;
        #pragma unroll
        for (int c = 0; c < 16; ++c) {
            float4 a = qs[i][c], b = ks[l][c];
            acc = fmaf(a.x, b.x, fmaf(a.y, b.y, fmaf(a.z, b.z, fmaf(a.w, b.w, acc))));
        }
        attn[((size_t)bh*Uq + i)*Lq + tile*128 + l] = acc * 0.125f;  // 1/sqrt(64)
    }
}

// ---------------------------------------------------------------------------
// Kernel 4: row softmax in-place on attn (block per row)
// ---------------------------------------------------------------------------
__global__ void k_softmax(float* __restrict__ attn) {
    __shared__ float red[256];
    int row = blockIdx.x, t = threadIdx.x;
    float* a = attn + (size_t)row * Lq;

    float4 v0 = ((float4*)a)[t];
    float4 v1 = ((float4*)a)[t + 256];

    float mx = fmaxf(fmaxf(fmaxf(v0.x, v0.y), fmaxf(v0.z, v0.w)),
                     fmaxf(fmaxf(v1.x, v1.y), fmaxf(v1.z, v1.w)));
    red[t] = mx; __syncthreads();
    for (int o = 128; o > 0; o >>= 1) { if (t < o) red[t] = fmaxf(red[t], red[t+o]); __syncthreads(); }
    mx = red[0]; __syncthreads();

    v0.x = expf(v0.x - mx); v0.y = expf(v0.y - mx);
    v0.z = expf(v0.z - mx); v0.w = expf(v0.w - mx);
    v1.x = expf(v1.x - mx); v1.y = expf(v1.y - mx);
    v1.z = expf(v1.z - mx); v1.w = expf(v1.w - mx);

    float s = v0.x + v0.y + v0.z + v0.w + v1.x + v1.y + v1.z + v1.w;
    red[t] = s; __syncthreads();
    for (int o = 128; o > 0; o >>= 1) { if (t < o) red[t] += red[t+o]; __syncthreads(); }
    float inv = 1.0f / red[0];

    v0.x *= inv; v0.y *= inv; v0.z *= inv; v0.w *= inv;
    v1.x *= inv; v1.y *= inv; v1.z *= inv; v1.w *= inv;
    ((float4*)a)[t]       = v0;
    ((float4*)a)[t + 256] = v1;
}

// ---------------------------------------------------------------------------
// Kernel 5: partial context = attn(chunk) @ V(chunk).  Block = (chunk, bh).
// ---------------------------------------------------------------------------
__global__ void k_ctx(const float* __restrict__ v, const float* __restrict__ attn) {
    __shared__ float4 vs[64][17];   // 64 x 64 f32, padded
    __shared__ float  as[Uq][64];   // 40 x 64 attn tile
    int bh = blockIdx.y, ch = blockIdx.x, t = threadIdx.x;
    int d = t & 63, ig = t >> 6;    // ig in 0..7

    float acc[5] = {0.f, 0.f, 0.f, 0.f, 0.f};

    for (int tl = 0; tl < 4; ++tl) {
        int l0 = ch*256 + tl*64;
        for (int i = t; i < 64*16; i += 512)
            vs[i >> 4][i & 15] = ((const float4*)(v + ((size_t)bh*Lq + l0)*Dq))[i];
        for (int i = t; i < Uq*64; i += 512)
            as[i >> 6][i & 63] = attn[((size_t)bh*Uq + (i >> 6))*Lq + l0 + (i & 63)];
        __syncthreads();

        #pragma unroll 4
        for (int l = 0; l < 64; ++l) {
            float vv = ((const float*)&vs[l][0])[d];
            #pragma unroll
            for (int r = 0; r < 5; ++r) acc[r] += as[ig + 8*r][l] * vv;
        }
        __syncthreads();
    }
    for (int r = 0; r < 5; ++r)
        g_part[(size_t)ch*CTXN + ((size_t)bh*Uq + ig + 8*r)*Dq + d] = acc[r];
}

// ---------------------------------------------------------------------------
// Kernel 6: reduce the 8 partials (fixed order -> deterministic)
// ---------------------------------------------------------------------------
__global__ void k_reduce(float* __restrict__ ctx) {
    int i = blockIdx.x*256 + threadIdx.x;
    if (i < CTXN) {
        float s = 0.f;
        #pragma unroll
        for (int c = 0; c < NCH; ++c) s += g_part[(size_t)c*CTXN + i];
        ctx[i] = s;
    }
}

// ---------------------------------------------------------------------------
extern "C" void kernel_launch(void* const* d_in, const int* in_sizes, int n_in,
                              void* d_out, int out_size) {
    const float* q   = (const float*)d_in[0];
    const float* k   = (const float*)d_in[1];
    const float* v   = (const float*)d_in[2];
    const int*   idx = (const int*)d_in[3];

    float* ctx  = (float*)d_out;          // (B,H,u,D) = 163840 f32
    float* attn = ctx + CTXN;             // (B,H,u,L) = 5242880 f32

    k_M<<<(BH*Lq*32)/256, 256>>>(q, k, idx);
    k_topk<<<BH, 256>>>();
    k_scores<<<dim3(Lq/128, BH), 256>>>(q, k, attn);
    k_softmax<<<BH*Uq, 256>>>(attn);
    k_ctx<<<dim3(NCH, BH), 512>>>(v, attn);
    k_reduce<<<(CTXN + 255)/256, 256>>>(ctx);
}

// round 3
// speedup vs baseline: 1.8159x; 1.8159x over previous
#include <cuda_runtime.h>
#include <math.h>

#define Bq   8
#define Hq   8
#define Lq   2048
#define Dq   64
#define Uq   40
#define BH   64
#define CTXN (BH*Uq*Dq)
#define NCH  8

// scratch (no allocations allowed)
__device__ float g_M[BH*Lq];
__device__ int   g_top[BH*Uq];
__device__ float g_part[NCH*CTXN];

// ---------------------------------------------------------------------------
// Kernel 1: M[bh,l] = max_s(q·k[idx]) - sum_s(q·k[idx]) / L
// Warp per (bh,l). 4 samples per iteration: lane = (g<<3)|e where g=sample
// slot, e=32B chunk of the 256B key row. K LDG.128s are coalesced (4 aligned
// 128B lines per instr). Reduction = 3 shfls per 4 samples (was 11/sample).
// ---------------------------------------------------------------------------
__global__ __launch_bounds__(256) void k_M(const float* __restrict__ q,
                                           const float* __restrict__ kk,
                                           const int* __restrict__ idx) {
    int gw   = (blockIdx.x * blockDim.x + threadIdx.x) >> 5;   // bh*Lq + l
    int lane = threadIdx.x & 31;
    int g = lane >> 3;          // sample slot 0..3
    int e = lane & 7;           // 32B chunk 0..7
    int bh = gw >> 11;
    int l  = gw & (Lq - 1);

    const float*  kbase = kk + (size_t)bh*Lq*Dq;
    const float4* qrow  = (const float4*)(q + ((size_t)bh*Lq + l)*Dq);

    // loop-invariant q chunk for this lane (8 floats)
    const float4 q0 = __ldg(qrow + 2*e);
    const float4 q1 = __ldg(qrow + 2*e + 1);

    const int* irow = idx + l*Uq;
    float mx = -INFINITY, sm = 0.f;

    #pragma unroll
    for (int i = 0; i < Uq/4; ++i) {            // 10 iterations x 4 samples
        int j = __ldg(irow + 4*i + g);          // same addr across 8 lanes
        const float4* kr = (const float4*)(kbase + (size_t)j*Dq);
        float4 a = __ldg(kr + 2*e);
        float4 b = __ldg(kr + 2*e + 1);
        float p = q0.x*a.x;
        p = fmaf(q0.y, a.y, p); p = fmaf(q0.z, a.z, p); p = fmaf(q0.w, a.w, p);
        p = fmaf(q1.x, b.x, p); p = fmaf(q1.y, b.y, p);
        p = fmaf(q1.z, b.z, p); p = fmaf(q1.w, b.w, p);
        // sum over e (8-lane group)
        p += __shfl_xor_sync(0xffffffffu, p, 4);
        p += __shfl_xor_sync(0xffffffffu, p, 2);
        p += __shfl_xor_sync(0xffffffffu, p, 1);
        mx = fmaxf(mx, p); sm += p;
    }
    // cross-group (4 groups carry disjoint sample subsets)
    mx = fmaxf(mx, __shfl_xor_sync(0xffffffffu, mx, 8));
    sm += __shfl_xor_sync(0xffffffffu, sm, 8);
    mx = fmaxf(mx, __shfl_xor_sync(0xffffffffu, mx, 16));
    sm += __shfl_xor_sync(0xffffffffu, sm, 16);

    if (lane == 0) g_M[gw] = mx - sm * (1.0f / (float)Lq);
}

// ---------------------------------------------------------------------------
// Kernel 2: top-40 of M per (bh), descending, ties -> lower index (jax order)
// ---------------------------------------------------------------------------
__global__ void k_topk() {
    __shared__ float sv[Lq];
    __shared__ float rv[256];
    __shared__ int   ri[256];
    int bh = blockIdx.x, t = threadIdx.x;

    for (int i = t; i < Lq; i += 256) sv[i] = g_M[bh*Lq + i];
    __syncthreads();

    for (int r = 0; r < Uq; ++r) {
        float bv = -INFINITY; int bi = Lq;
        for (int i = t; i < Lq; i += 256) {
            float x = sv[i];
            if (x > bv || (x == bv && i < bi)) { bv = x; bi = i; }
        }
        rv[t] = bv; ri[t] = bi;
        __syncthreads();
        for (int o = 128; o > 0; o >>= 1) {
            if (t < o) {
                float x = rv[t+o]; int j = ri[t+o];
                if (x > rv[t] || (x == rv[t] && j < ri[t])) { rv[t] = x; ri[t] = j; }
            }
            __syncthreads();
        }
        if (t == 0) { g_top[bh*Uq + r] = ri[0]; sv[ri[0]] = -INFINITY; }
        __syncthreads();
    }
}

// ---------------------------------------------------------------------------
// Kernel 3: raw scaled scores -> attn buffer.  Block = (bh, 128-key tile).
// ---------------------------------------------------------------------------
__global__ void k_scores(const float* __restrict__ q, const float* __restrict__ kk,
                         float* __restrict__ attn) {
    __shared__ float4 qs[Uq][16];    // 40 x 64 f32
    __shared__ float4 ks[128][17];   // 128 x 64 f32, padded
    int bh = blockIdx.y, tile = blockIdx.x, t = threadIdx.x;

    const float* qb = q  + (size_t)bh*Lq*Dq;
    const float* kb = kk + ((size_t)bh*Lq + tile*128)*Dq;

    for (int i = t; i < Uq*Dq; i += 256) {
        int r = i >> 6, d = i & 63;
        ((float*)&qs[r][0])[d] = qb[(size_t)g_top[bh*Uq + r]*Dq + d];
    }
    for (int i = t; i < 128*16; i += 256)
        ks[i >> 4][i & 15] = ((const float4*)kb)[i];
    __syncthreads();

    for (int p = t; p < Uq*128; p += 256) {
        int i = p >> 7, l = p & 127;
        float acc = 0.f;
        #pragma unroll
        for (int c = 0; c < 16; ++c) {
            float4 a = qs[i][c], b = ks[l][c];
            acc = fmaf(a.x, b.x, fmaf(a.y, b.y, fmaf(a.z, b.z, fmaf(a.w, b.w, acc))));
        }
        attn[((size_t)bh*Uq + i)*Lq + tile*128 + l] = acc * 0.125f;  // 1/sqrt(64)
    }
}

// ---------------------------------------------------------------------------
// Kernel 4: row softmax in-place on attn (block per row)
// ---------------------------------------------------------------------------
__global__ void k_softmax(float* __restrict__ attn) {
    __shared__ float red[256];
    int row = blockIdx.x, t = threadIdx.x;
    float* a = attn + (size_t)row * Lq;

    float4 v0 = ((float4*)a)[t];
    float4 v1 = ((float4*)a)[t + 256];

    float mx = fmaxf(fmaxf(fmaxf(v0.x, v0.y), fmaxf(v0.z, v0.w)),
                     fmaxf(fmaxf(v1.x, v1.y), fmaxf(v1.z, v1.w)));
    red[t] = mx; __syncthreads();
    for (int o = 128; o > 0; o >>= 1) { if (t < o) red[t] = fmaxf(red[t], red[t+o]); __syncthreads(); }
    mx = red[0]; __syncthreads();

    v0.x = expf(v0.x - mx); v0.y = expf(v0.y - mx);
    v0.z = expf(v0.z - mx); v0.w = expf(v0.w - mx);
    v1.x = expf(v1.x - mx); v1.y = expf(v1.y - mx);
    v1.z = expf(v1.z - mx); v1.w = expf(v1.w - mx);

    float s = v0.x + v0.y + v0.z + v0.w + v1.x + v1.y + v1.z + v1.w;
    red[t] = s; __syncthreads();
    for (int o = 128; o > 0; o >>= 1) { if (t < o) red[t] += red[t+o]; __syncthreads(); }
    float inv = 1.0f / red[0];

    v0.x *= inv; v0.y *= inv; v0.z *= inv; v0.w *= inv;
    v1.x *= inv; v1.y *= inv; v1.z *= inv; v1.w *= inv;
    ((float4*)a)[t]       = v0;
    ((float4*)a)[t + 256] = v1;
}

// ---------------------------------------------------------------------------
// Kernel 5: partial context = attn(chunk) @ V(chunk).  Block = (chunk, bh).
// ---------------------------------------------------------------------------
__global__ void k_ctx(const float* __restrict__ v, const float* __restrict__ attn) {
    __shared__ float4 vs[64][17];   // 64 x 64 f32, padded
    __shared__ float  as[Uq][64];   // 40 x 64 attn tile
    int bh = blockIdx.y, ch = blockIdx.x, t = threadIdx.x;
    int d = t & 63, ig = t >> 6;    // ig in 0..7

    float acc[5] = {0.f, 0.f, 0.f, 0.f, 0.f};

    for (int tl = 0; tl < 4; ++tl) {
        int l0 = ch*256 + tl*64;
        for (int i = t; i < 64*16; i += 512)
            vs[i >> 4][i & 15] = ((const float4*)(v + ((size_t)bh*Lq + l0)*Dq))[i];
        for (int i = t; i < Uq*64; i += 512)
            as[i >> 6][i & 63] = attn[((size_t)bh*Uq + (i >> 6))*Lq + l0 + (i & 63)];
        __syncthreads();

        #pragma unroll 4
        for (int l = 0; l < 64; ++l) {
            float vv = ((const float*)&vs[l][0])[d];
            #pragma unroll
            for (int r = 0; r < 5; ++r) acc[r] += as[ig + 8*r][l] * vv;
        }
        __syncthreads();
    }
    for (int r = 0; r < 5; ++r)
        g_part[(size_t)ch*CTXN + ((size_t)bh*Uq + ig + 8*r)*Dq + d] = acc[r];
}

// ---------------------------------------------------------------------------
// Kernel 6: reduce the 8 partials (fixed order -> deterministic)
// ---------------------------------------------------------------------------
__global__ void k_reduce(float* __restrict__ ctx) {
    int i = blockIdx.x*256 + threadIdx.x;
    if (i < CTXN) {
        float s = 0.f;
        #pragma unroll
        for (int c = 0; c < NCH; ++c) s += g_part[(size_t)c*CTXN + i];
        ctx[i] = s;
    }
}

// ---------------------------------------------------------------------------
extern "C" void kernel_launch(void* const* d_in, const int* in_sizes, int n_in,
                              void* d_out, int out_size) {
    const float* q   = (const float*)d_in[0];
    const float* k   = (const float*)d_in[1];
    const float* v   = (const float*)d_in[2];
    const int*   idx = (const int*)d_in[3];

    float* ctx  = (float*)d_out;          // (B,H,u,D) = 163840 f32
    float* attn = ctx + CTXN;             // (B,H,u,L) = 5242880 f32

    k_M<<<(BH*Lq*32)/256, 256>>>(q, k, idx);
    k_topk<<<BH, 256>>>();
    k_scores<<<dim3(Lq/128, BH), 256>>>(q, k, attn);
    k_softmax<<<BH*Uq, 256>>>(attn);
    k_ctx<<<dim3(NCH, BH), 512>>>(v, attn);
    k_reduce<<<(CTXN + 255)/256, 256>>>(ctx);
}

// round 4
// speedup vs baseline: 2.0264x; 1.1159x over previous
#include <cuda_runtime.h>
#include <math.h>

#define Bq   8
#define Hq   8
#define Lq   2048
#define Dq   64
#define Uq   40
#define BH   64
#define CTXN (BH*Uq*Dq)
#define NCH  8

// scratch (no allocations allowed)
__device__ float g_M[BH*Lq];
__device__ int   g_top[BH*Uq];
__device__ float g_part[NCH*CTXN];

// ---------------------------------------------------------------------------
// Kernel 1: M[bh,l] = max_s(q·k[idx]) - sum_s(q·k[idx]) / L   (unchanged, R3)
// ---------------------------------------------------------------------------
__global__ __launch_bounds__(256) void k_M(const float* __restrict__ q,
                                           const float* __restrict__ kk,
                                           const int* __restrict__ idx) {
    int gw   = (blockIdx.x * blockDim.x + threadIdx.x) >> 5;   // bh*Lq + l
    int lane = threadIdx.x & 31;
    int g = lane >> 3;          // sample slot 0..3
    int e = lane & 7;           // 32B chunk 0..7
    int bh = gw >> 11;
    int l  = gw & (Lq - 1);

    const float*  kbase = kk + (size_t)bh*Lq*Dq;
    const float4* qrow  = (const float4*)(q + ((size_t)bh*Lq + l)*Dq);

    const float4 q0 = __ldg(qrow + 2*e);
    const float4 q1 = __ldg(qrow + 2*e + 1);

    const int* irow = idx + l*Uq;
    float mx = -INFINITY, sm = 0.f;

    #pragma unroll
    for (int i = 0; i < Uq/4; ++i) {
        int j = __ldg(irow + 4*i + g);
        const float4* kr = (const float4*)(kbase + (size_t)j*Dq);
        float4 a = __ldg(kr + 2*e);
        float4 b = __ldg(kr + 2*e + 1);
        float p = q0.x*a.x;
        p = fmaf(q0.y, a.y, p); p = fmaf(q0.z, a.z, p); p = fmaf(q0.w, a.w, p);
        p = fmaf(q1.x, b.x, p); p = fmaf(q1.y, b.y, p);
        p = fmaf(q1.z, b.z, p); p = fmaf(q1.w, b.w, p);
        p += __shfl_xor_sync(0xffffffffu, p, 4);
        p += __shfl_xor_sync(0xffffffffu, p, 2);
        p += __shfl_xor_sync(0xffffffffu, p, 1);
        mx = fmaxf(mx, p); sm += p;
    }
    mx = fmaxf(mx, __shfl_xor_sync(0xffffffffu, mx, 8));
    sm += __shfl_xor_sync(0xffffffffu, sm, 8);
    mx = fmaxf(mx, __shfl_xor_sync(0xffffffffu, mx, 16));
    sm += __shfl_xor_sync(0xffffffffu, sm, 16);

    if (lane == 0) g_M[gw] = mx - sm * (1.0f / (float)Lq);
}

// ---------------------------------------------------------------------------
// Kernel 2: top-40 of M per (bh)  (unchanged)
// ---------------------------------------------------------------------------
__global__ void k_topk() {
    __shared__ float sv[Lq];
    __shared__ float rv[256];
    __shared__ int   ri[256];
    int bh = blockIdx.x, t = threadIdx.x;

    for (int i = t; i < Lq; i += 256) sv[i] = g_M[bh*Lq + i];
    __syncthreads();

    for (int r = 0; r < Uq; ++r) {
        float bv = -INFINITY; int bi = Lq;
        for (int i = t; i < Lq; i += 256) {
            float x = sv[i];
            if (x > bv || (x == bv && i < bi)) { bv = x; bi = i; }
        }
        rv[t] = bv; ri[t] = bi;
        __syncthreads();
        for (int o = 128; o > 0; o >>= 1) {
            if (t < o) {
                float x = rv[t+o]; int j = ri[t+o];
                if (x > rv[t] || (x == rv[t] && j < ri[t])) { rv[t] = x; ri[t] = j; }
            }
            __syncthreads();
        }
        if (t == 0) { g_top[bh*Uq + r] = ri[0]; sv[ri[0]] = -INFINITY; }
        __syncthreads();
    }
}

// ---------------------------------------------------------------------------
// Kernel 3: scores, 4x4 register-tiled.  Block=(bh, 128-l tile), 320 threads.
// warp w owns i-quad 4w..4w+3; lane owns l in {lane+32j}.
// ---------------------------------------------------------------------------
__global__ __launch_bounds__(320) void k_scores(const float* __restrict__ q,
                                                const float* __restrict__ kk,
                                                float* __restrict__ attn) {
    __shared__ float qs[Uq][68];     // 40x64, 68-word rows (16B-aligned, cf-free)
    __shared__ float ks[128][68];
    int bh = blockIdx.y, tile = blockIdx.x, t = threadIdx.x;
    int w = t >> 5, lane = t & 31;

    const float* qb = q  + (size_t)bh*Lq*Dq;
    const float* kb = kk + ((size_t)bh*Lq + tile*128)*Dq;

    for (int i = t; i < Uq*16; i += 320) {
        int r = i >> 4, c4 = i & 15;
        float4 val = *(const float4*)(qb + (size_t)g_top[bh*Uq + r]*Dq + c4*4);
        *(float4*)&qs[r][c4*4] = val;
    }
    for (int i = t; i < 128*16; i += 320) {
        int l = i >> 4, c4 = i & 15;
        *(float4*)&ks[l][c4*4] = ((const float4*)(kb + (size_t)l*Dq))[c4];
    }
    __syncthreads();

    float acc[4][4] = {};
    #pragma unroll 4
    for (int c = 0; c < 64; c += 4) {
        float4 kr[4], qr[4];
        #pragma unroll
        for (int j = 0; j < 4; ++j) kr[j] = *(const float4*)&ks[lane + 32*j][c];
        #pragma unroll
        for (int j = 0; j < 4; ++j) qr[j] = *(const float4*)&qs[4*w + j][c];
        #pragma unroll
        for (int ji = 0; ji < 4; ++ji)
            #pragma unroll
            for (int jl = 0; jl < 4; ++jl) {
                acc[ji][jl] = fmaf(qr[ji].x, kr[jl].x, acc[ji][jl]);
                acc[ji][jl] = fmaf(qr[ji].y, kr[jl].y, acc[ji][jl]);
                acc[ji][jl] = fmaf(qr[ji].z, kr[jl].z, acc[ji][jl]);
                acc[ji][jl] = fmaf(qr[ji].w, kr[jl].w, acc[ji][jl]);
            }
    }
    #pragma unroll
    for (int ji = 0; ji < 4; ++ji) {
        int i = 4*w + ji;
        #pragma unroll
        for (int jl = 0; jl < 4; ++jl)
            attn[((size_t)bh*Uq + i)*Lq + tile*128 + lane + 32*jl] = acc[ji][jl] * 0.125f;
    }
}

// ---------------------------------------------------------------------------
// Kernel 4: row softmax (unchanged)
// ---------------------------------------------------------------------------
__global__ void k_softmax(float* __restrict__ attn) {
    __shared__ float red[256];
    int row = blockIdx.x, t = threadIdx.x;
    float* a = attn + (size_t)row * Lq;

    float4 v0 = ((float4*)a)[t];
    float4 v1 = ((float4*)a)[t + 256];

    float mx = fmaxf(fmaxf(fmaxf(v0.x, v0.y), fmaxf(v0.z, v0.w)),
                     fmaxf(fmaxf(v1.x, v1.y), fmaxf(v1.z, v1.w)));
    red[t] = mx; __syncthreads();
    for (int o = 128; o > 0; o >>= 1) { if (t < o) red[t] = fmaxf(red[t], red[t+o]); __syncthreads(); }
    mx = red[0]; __syncthreads();

    v0.x = expf(v0.x - mx); v0.y = expf(v0.y - mx);
    v0.z = expf(v0.z - mx); v0.w = expf(v0.w - mx);
    v1.x = expf(v1.x - mx); v1.y = expf(v1.y - mx);
    v1.z = expf(v1.z - mx); v1.w = expf(v1.w - mx);

    float s = v0.x + v0.y + v0.z + v0.w + v1.x + v1.y + v1.z + v1.w;
    red[t] = s; __syncthreads();
    for (int o = 128; o > 0; o >>= 1) { if (t < o) red[t] += red[t+o]; __syncthreads(); }
    float inv = 1.0f / red[0];

    v0.x *= inv; v0.y *= inv; v0.z *= inv; v0.w *= inv;
    v1.x *= inv; v1.y *= inv; v1.z *= inv; v1.w *= inv;
    ((float4*)a)[t]       = v0;
    ((float4*)a)[t + 256] = v1;
}

// ---------------------------------------------------------------------------
// Kernel 5: context partials, register-tiled.  Block=(ch, bh), 320 threads.
// warp w owns i-quad; lane owns d-pair {2*lane, 2*lane+1}. K-loop 256 = 4x64.
// ---------------------------------------------------------------------------
__global__ __launch_bounds__(320) void k_ctx(const float* __restrict__ v,
                                             const float* __restrict__ attn) {
    __shared__ float2 vs2[64][32];     // 64 k-rows x 64 d (float2), cf-free
    __shared__ float  as_t[64][44];    // transposed attn tile [k][i], 16B rows
    int bh = blockIdx.y, ch = blockIdx.x, t = threadIdx.x;
    int w = t >> 5, lane = t & 31;

    float2 c0 = {0.f,0.f}, c1 = {0.f,0.f}, c2 = {0.f,0.f}, c3 = {0.f,0.f};

    for (int tl = 0; tl < 4; ++tl) {
        int l0 = ch*256 + tl*64;
        // V: 64 rows x 64 floats, bulk float4 copy
        for (int i = t; i < 64*16; i += 320) {
            int k = i >> 4, c4 = i & 15;
            *(float4*)((float*)&vs2[k][0] + c4*4) =
                ((const float4*)(v + ((size_t)bh*Lq + l0 + k)*Dq))[c4];
        }
        // attn tile transposed: read [i][k] coalesced, store as_t[k][i]
        for (int i = t; i < Uq*64; i += 320) {
            int r = i >> 6, k = i & 63;
            as_t[k][r] = attn[((size_t)bh*Uq + r)*Lq + l0 + k];
        }
        __syncthreads();

        #pragma unroll 4
        for (int k = 0; k < 64; ++k) {
            float4 av = *(const float4*)&as_t[k][4*w];  // broadcast, 1 phase
            float2 vv = vs2[k][lane];                    // 256B coalesced
            c0.x = fmaf(av.x, vv.x, c0.x); c0.y = fmaf(av.x, vv.y, c0.y);
            c1.x = fmaf(av.y, vv.x, c1.x); c1.y = fmaf(av.y, vv.y, c1.y);
            c2.x = fmaf(av.z, vv.x, c2.x); c2.y = fmaf(av.z, vv.y, c2.y);
            c3.x = fmaf(av.w, vv.x, c3.x); c3.y = fmaf(av.w, vv.y, c3.y);
        }
        __syncthreads();
    }

    float* gp = g_part + (size_t)ch*CTXN + ((size_t)bh*Uq + 4*w)*Dq + 2*lane;
    *(float2*)(gp)          = c0;
    *(float2*)(gp + Dq)     = c1;
    *(float2*)(gp + 2*Dq)   = c2;
    *(float2*)(gp + 3*Dq)   = c3;
}

// ---------------------------------------------------------------------------
// Kernel 6: reduce the 8 partials (fixed order -> deterministic)
// ---------------------------------------------------------------------------
__global__ void k_reduce(float* __restrict__ ctx) {
    int i = blockIdx.x*256 + threadIdx.x;
    if (i < CTXN) {
        float s = 0.f;
        #pragma unroll
        for (int c = 0; c < NCH; ++c) s += g_part[(size_t)c*CTXN + i];
        ctx[i] = s;
    }
}

// ---------------------------------------------------------------------------
extern "C" void kernel_launch(void* const* d_in, const int* in_sizes, int n_in,
                              void* d_out, int out_size) {
    const float* q   = (const float*)d_in[0];
    const float* k   = (const float*)d_in[1];
    const float* v   = (const float*)d_in[2];
    const int*   idx = (const int*)d_in[3];

    float* ctx  = (float*)d_out;          // (B,H,u,D) = 163840 f32
    float* attn = ctx + CTXN;             // (B,H,u,L) = 5242880 f32

    k_M<<<(BH*Lq*32)/256, 256>>>(q, k, idx);
    k_topk<<<BH, 256>>>();
    k_scores<<<dim3(Lq/128, BH), 320>>>(q, k, attn);
    k_softmax<<<BH*Uq, 256>>>(attn);
    k_ctx<<<dim3(NCH, BH), 320>>>(v, attn);
    k_reduce<<<(CTXN + 255)/256, 256>>>(ctx);
}